// round 5
// baseline (speedup 1.0000x reference)
#include <cuda_runtime.h>

#define NN 20000
#define NE 320000
#define NG 256
#define NA 23
#define NB 7
#define M0 64
#define M1 24
#define M2 16
#define MTOT 104
#define YDIM 728
#define MDIM 64
#define OFF1 64
#define OFF2 136
#define SME 64

__device__ __align__(16) float g_y[(size_t)NN * YDIM];   // A1-scaled x@W
__device__ __align__(16) float g_t[(size_t)NE * MTOT];   // per-edge t rows
__device__ __align__(16) float g_m[(size_t)NN * MDIM];
__device__ int g_cnt_s[NN], g_cur_s[NN];
__device__ int g_cnt_d[NN], g_cur_d[NN], g_start_d[NN];
__device__ int g_sperm[NE], g_ssrc[NE];
__device__ int g_deid[NE], g_desrc[NE];

#define A1  0.078811041f
#define C0  0.047245559f
#define C1  0.044543540f
#define C2  0.042257713f
#define S3  1.7320508075688772f
#define S5  2.23606797749979f
#define S15 3.872983346207417f

__global__ void k_zero(float* __restrict__ out) {
    int i = blockIdx.x * blockDim.x + threadIdx.x;
    int stride = gridDim.x * blockDim.x;
    for (int j = i; j < NN; j += stride) { g_cnt_s[j] = 0; g_cnt_d[j] = 0; }
    for (int j = i; j < NG; j += stride) out[j] = 0.f;
}

__global__ void k_count(const int* __restrict__ ei) {
    int e = blockIdx.x * blockDim.x + threadIdx.x;
    if (e < NE) {
        atomicAdd(&g_cnt_s[ei[e]], 1);
        atomicAdd(&g_cnt_d[ei[NE + e]], 1);
    }
}

__global__ void __launch_bounds__(1024) k_scan() {
    __shared__ int sums[1024];
    int t = threadIdx.x;
    int base = t * 20;

    // ---- src scan ----
    {
        int local[20]; int s = 0;
#pragma unroll
        for (int i = 0; i < 20; i++) {
            int idx = base + i;
            int c = (idx < NN) ? g_cnt_s[idx] : 0;
            local[i] = s; s += c;
        }
        sums[t] = s;
        __syncthreads();
        for (int d = 1; d < 1024; d <<= 1) {
            int v = (t >= d) ? sums[t - d] : 0;
            __syncthreads();
            if (t >= d) sums[t] += v;
            __syncthreads();
        }
        int excl = (t == 0) ? 0 : sums[t - 1];
#pragma unroll
        for (int i = 0; i < 20; i++) {
            int idx = base + i;
            if (idx < NN) g_cur_s[idx] = excl + local[i];
        }
        __syncthreads();
    }
    // ---- dst scan ----
    {
        int local[20]; int s = 0;
#pragma unroll
        for (int i = 0; i < 20; i++) {
            int idx = base + i;
            int c = (idx < NN) ? g_cnt_d[idx] : 0;
            local[i] = s; s += c;
        }
        sums[t] = s;
        __syncthreads();
        for (int d = 1; d < 1024; d <<= 1) {
            int v = (t >= d) ? sums[t - d] : 0;
            __syncthreads();
            if (t >= d) sums[t] += v;
            __syncthreads();
        }
        int excl = (t == 0) ? 0 : sums[t - 1];
#pragma unroll
        for (int i = 0; i < 20; i++) {
            int idx = base + i;
            if (idx < NN) { g_cur_d[idx] = excl + local[i]; g_start_d[idx] = excl + local[i]; }
        }
    }
}

__global__ void k_fill(const int* __restrict__ ei) {
    int e = blockIdx.x * blockDim.x + threadIdx.x;
    if (e >= NE) return;
    int src = ei[e];
    int dst = ei[NE + e];
    int ps = atomicAdd(&g_cur_s[src], 1);
    g_sperm[ps] = e;
    g_ssrc[ps] = src;
    int pd = atomicAdd(&g_cur_d[dst], 1);
    g_deid[pd] = e;
    g_desrc[pd] = src;
}

// -------- nodeY: y = A1 * (x @ W), weights in registers ----------------------
__global__ void __launch_bounds__(448) k_nodeY_a(
    const float* __restrict__ x, const float* __restrict__ W1)
{
    __shared__ float xs[NA];
    int v = threadIdx.x / M0;
    int w = threadIdx.x % M0;
    float wreg[NA];
#pragma unroll
    for (int u = 0; u < NA; u++) wreg[u] = W1[u * 448 + threadIdx.x];

    for (int n = blockIdx.x; n < NN; n += gridDim.x) {
        __syncthreads();
        if (threadIdx.x < NA) xs[threadIdx.x] = x[n * NA + threadIdx.x];
        __syncthreads();
        float r = 0.f;
#pragma unroll
        for (int u = 0; u < NA; u++) r = fmaf(xs[u], wreg[u], r);
        g_y[(long long)n * YDIM + v * MTOT + w] = A1 * r;
    }
}

__global__ void __launch_bounds__(320) k_nodeY_b(
    const float* __restrict__ x, const float* __restrict__ W2,
    const float* __restrict__ W3)
{
    __shared__ float xs[NA];
    bool active = threadIdx.x < 280;
    int v = threadIdx.x / 40;
    int j = threadIdx.x % 40;
    float wreg[NA];
    if (active) {
#pragma unroll
        for (int u = 0; u < NA; u++)
            wreg[u] = (j < M1) ? W2[(u * NB + v) * M1 + j]
                               : W3[(u * NB + v) * M2 + (j - M1)];
    }
    for (int n = blockIdx.x; n < NN; n += gridDim.x) {
        __syncthreads();
        if (threadIdx.x < NA) xs[threadIdx.x] = x[n * NA + threadIdx.x];
        __syncthreads();
        if (!active) continue;
        float r = 0.f;
#pragma unroll
        for (int u = 0; u < NA; u++) r = fmaf(xs[u], wreg[u], r);
        g_y[(long long)n * YDIM + v * MTOT + 64 + j] = A1 * r;
    }
}

// -------- t-kernel: t[e, 0:104] = A1 * sum_v ea[e,v] * y[src, v, :] ----------
// src-sorted, 2 threads per edge, y loads warp-broadcast.
__global__ void __launch_bounds__(256) k_tcomp(const float* __restrict__ ea)
{
    int gid = blockIdx.x * 256 + threadIdx.x;
    int p = gid >> 1;
    int half = gid & 1;
    if (p >= NE) return;
    int e = g_sperm[p];
    int src = g_ssrc[p];

    float4 acc[13];
#pragma unroll
    for (int i = 0; i < 13; i++) acc[i] = make_float4(0.f, 0.f, 0.f, 0.f);

    const float* yrow = g_y + (long long)src * YDIM + half * 52;
#pragma unroll
    for (int v = 0; v < NB; v++) {
        float eav = __ldg(ea + e * NB + v);
        const float4* yp = (const float4*)(yrow + v * MTOT);
#pragma unroll
        for (int i = 0; i < 13; i++) {
            float4 yv = __ldg(yp + i);
            acc[i].x = fmaf(eav, yv.x, acc[i].x);
            acc[i].y = fmaf(eav, yv.y, acc[i].y);
            acc[i].z = fmaf(eav, yv.z, acc[i].z);
            acc[i].w = fmaf(eav, yv.w, acc[i].w);
        }
    }
    float4* tp = (float4*)(g_t + (long long)e * MTOT + half * 52);
#pragma unroll
    for (int i = 0; i < 13; i++) tp[i] = acc[i];
}

// -------- accum: block per dst node, register accumulation, fused nodeV ------
__global__ void __launch_bounds__(224) k_accum(
    const float* __restrict__ pos, const float* __restrict__ V1,
    const float* __restrict__ V2, const float* __restrict__ V3)
{
    __shared__ float4 st[4][26];
    __shared__ float ssh[4][8];
    __shared__ float nf[216];
    __shared__ float Vs[728];
    __shared__ float sdp[3];
    __shared__ int se[SME], ss[SME];

    int n = blockIdx.x;
    int tid = threadIdx.x;

    for (int i = tid; i < 728; i += 224)
        Vs[i] = (i < 448) ? V1[i] : (i < 616) ? V2[i - 448] : V3[i - 616];
    if (tid < 3) sdp[tid] = pos[n * 3 + tid];

    // per-thread feature mapping
    int w = 0, sidx = 0; bool k0 = true;
    if (tid < 64) { w = tid; }
    else if (tid < 136) { int q = tid - 64;  w = 64 + q / 3; sidx = q % 3;     k0 = false; }
    else if (tid < 216) { int q = tid - 136; w = 88 + q / 5; sidx = 3 + q % 5; k0 = false; }

    int start = g_start_d[n];
    int cnt = g_cnt_d[n];
    float acc = 0.f;

#define LOADBUF(idx, b) do { \
    if (tid < 26) st[b][tid] = __ldg((const float4*)(g_t + (long long)se[idx] * MTOT) + tid); \
    else if (tid == 32) { \
        int s_ = ss[idx]; \
        float px = pos[s_*3+0] - sdp[0]; \
        float py = pos[s_*3+1] - sdp[1]; \
        float pz = pos[s_*3+2] - sdp[2]; \
        ssh[b][0] = S3*px; ssh[b][1] = S3*py; ssh[b][2] = S3*pz; \
        float r2 = px*px + py*py + pz*pz; \
        ssh[b][3] = S15*px*py; ssh[b][4] = S15*py*pz; \
        ssh[b][5] = 0.5f*S5*(3.f*pz*pz - r2); \
        ssh[b][6] = S15*px*pz; ssh[b][7] = 0.5f*S15*(px*px - py*py); \
    } } while (0)

    for (int chunk = 0; chunk < cnt; chunk += SME) {
        int c = min(SME, cnt - chunk);
        __syncthreads();
        if (tid < c) {
            se[tid] = g_deid[start + chunk + tid];
            ss[tid] = g_desrc[start + chunk + tid];
        }
        __syncthreads();
        int npf = c < 3 ? c : 3;
        for (int q = 0; q < npf; q++) LOADBUF(q, q & 3);
        for (int i = 0; i < c; i++) {
            __syncthreads();
            if (i + 3 < c) LOADBUF(i + 3, (i + 3) & 3);
            int b = i & 3;
            float tval = ((const float*)st[b])[w];
            float mlt = k0 ? 1.0f : ssh[b][sidx];
            if (tid < 216) acc = fmaf(tval, mlt, acc);
        }
    }

    __syncthreads();
    if (tid < 216) nf[tid] = acc;
    __syncthreads();

    if (tid < 63) {
        float r = 0.f;
        if (tid < 7) {
            int v = tid;
            for (int u = 0; u < M0; u++) r = fmaf(nf[u], Vs[u * NB + v], r);
            r *= C0;
        } else if (tid < 28) {
            int t2 = tid - 7; int v = t2 / 3; int m = t2 - 3 * v;
            for (int u = 0; u < M1; u++) r = fmaf(nf[OFF1 + u*3 + m], Vs[448 + u*NB + v], r);
            r *= C1;
        } else {
            int t2 = tid - 28; int v = t2 / 5; int m = t2 - 5 * v;
            for (int u = 0; u < M2; u++) r = fmaf(nf[OFF2 + u*5 + m], Vs[616 + u*NB + v], r);
            r *= C2;
        }
        g_m[(long long)n * MDIM + tid] = r;
    }
}

// -------- pass2: warp per dst node over CSR, fused graph reduction -----------
__global__ void __launch_bounds__(256) k_pass2(
    const float* __restrict__ pos, const float* __restrict__ ea,
    const int* __restrict__ batch, float* __restrict__ out)
{
    int warp = (blockIdx.x * 256 + threadIdx.x) >> 5;
    int lane = threadIdx.x & 31;
    if (warp >= NN) return;
    int n = warp;
    int start = g_start_d[n];
    int cnt = g_cnt_d[n];

    float dpx = pos[n*3+0], dpy = pos[n*3+1], dpz = pos[n*3+2];
    float gsum = 0.f;

    for (int i = lane; i < cnt; i += 32) {
        int e = g_deid[start + i];
        int s = g_desrc[start + i];

        float px = pos[s*3+0] - dpx;
        float py = pos[s*3+1] - dpy;
        float pz = pos[s*3+2] - dpz;
        float sh1x = S3*px, sh1y = S3*py, sh1z = S3*pz;
        float r2 = px*px + py*py + pz*pz;
        float sh2_0 = S15*px*py;
        float sh2_1 = S15*py*pz;
        float sh2_2 = 0.5f*S5*(3.f*pz*pz - r2);
        float sh2_3 = S15*px*pz;
        float sh2_4 = 0.5f*S15*(px*px - py*py);

        float eav[NB];
#pragma unroll
        for (int v = 0; v < NB; v++) eav[v] = __ldg(ea + e * NB + v);

        float mreg[64];
        const float4* mp = (const float4*)(g_m + (long long)s * MDIM);
#pragma unroll
        for (int q = 0; q < 16; q++) ((float4*)mreg)[q] = __ldg(mp + q);

        float g = 0.f;
#pragma unroll
        for (int v = 0; v < NB; v++) {
            const float* m1v = mreg + 7 + v*3;
            const float* m2v = mreg + 28 + v*5;
            float t = mreg[v];
            t = fmaf(sh1x, m1v[0], t);
            t = fmaf(sh1y, m1v[1], t);
            t = fmaf(sh1z, m1v[2], t);
            t = fmaf(sh2_0, m2v[0], t);
            t = fmaf(sh2_1, m2v[1], t);
            t = fmaf(sh2_2, m2v[2], t);
            t = fmaf(sh2_3, m2v[3], t);
            t = fmaf(sh2_4, m2v[4], t);
            g = fmaf(eav[v], t, g);
        }
        gsum += g;
    }

#pragma unroll
    for (int off = 16; off > 0; off >>= 1)
        gsum += __shfl_xor_sync(0xFFFFFFFFu, gsum, off);

    if (lane == 0) atomicAdd(&out[batch[n]], gsum);
}

extern "C" void kernel_launch(void* const* d_in, const int* in_sizes, int n_in,
                              void* d_out, int out_size) {
    const float* pos   = (const float*)d_in[0];
    const float* x     = (const float*)d_in[1];
    const float* ea    = (const float*)d_in[2];
    const int*   ei    = (const int*)d_in[3];
    const int*   batch = (const int*)d_in[4];
    const float* W1    = (const float*)d_in[5];
    const float* W2    = (const float*)d_in[6];
    const float* W3    = (const float*)d_in[7];
    const float* V1    = (const float*)d_in[8];
    const float* V2    = (const float*)d_in[9];
    const float* V3    = (const float*)d_in[10];
    float* out = (float*)d_out;

    k_zero<<<160, 256>>>(out);
    k_count<<<(NE + 255) / 256, 256>>>(ei);
    k_scan<<<1, 1024>>>();
    k_fill<<<(NE + 255) / 256, 256>>>(ei);
    k_nodeY_a<<<1184, 448>>>(x, W1);
    k_nodeY_b<<<1184, 320>>>(x, W2, W3);
    k_tcomp<<<(2 * NE) / 256, 256>>>(ea);
    k_accum<<<NN, 224>>>(pos, V1, V2, V3);
    k_pass2<<<(NN * 32) / 256, 256>>>(pos, ea, batch, out);
}

// round 6
// speedup vs baseline: 1.3518x; 1.3518x over previous
#include <cuda_runtime.h>

#define NN 20000
#define NE 320000
#define NG 256
#define NA 23
#define NB 7
#define M0 64
#define M1 24
#define M2 16
#define MTOT 104
#define YDIM 728
#define MDIM 64
#define OFF1 64
#define OFF2 136

__device__ __align__(16) float g_y[(size_t)NN * YDIM];   // A1-scaled x@W
__device__ __align__(16) float g_t[(size_t)NE * MTOT];   // t rows in dst-sorted order
__device__ __align__(16) float g_m[(size_t)NN * MDIM];
__device__ int g_cnt_s[NN], g_cur_s[NN];
__device__ int g_cnt_d[NN], g_cur_d[NN], g_start_d[NN];
__device__ int g_sperm[NE], g_ssrc[NE], g_spos[NE];      // src-order: edge id, src, dst-pos
__device__ int g_deid[NE], g_desrc[NE];                  // dst-order: edge id, src

#define A1  0.078811041f
#define C0  0.047245559f
#define C1  0.044543540f
#define C2  0.042257713f
#define S3  1.7320508075688772f
#define S5  2.23606797749979f
#define S15 3.872983346207417f

__global__ void k_zero(float* __restrict__ out) {
    int i = blockIdx.x * blockDim.x + threadIdx.x;
    int stride = gridDim.x * blockDim.x;
    for (int j = i; j < NN; j += stride) { g_cnt_s[j] = 0; g_cnt_d[j] = 0; }
    for (int j = i; j < NG; j += stride) out[j] = 0.f;
}

__global__ void k_count(const int* __restrict__ ei) {
    int e = blockIdx.x * blockDim.x + threadIdx.x;
    if (e < NE) {
        atomicAdd(&g_cnt_s[ei[e]], 1);
        atomicAdd(&g_cnt_d[ei[NE + e]], 1);
    }
}

__global__ void __launch_bounds__(1024) k_scan() {
    __shared__ int sums[1024];
    int t = threadIdx.x;
    int base = t * 20;
    {
        int local[20]; int s = 0;
#pragma unroll
        for (int i = 0; i < 20; i++) {
            int idx = base + i;
            int c = (idx < NN) ? g_cnt_s[idx] : 0;
            local[i] = s; s += c;
        }
        sums[t] = s;
        __syncthreads();
        for (int d = 1; d < 1024; d <<= 1) {
            int v = (t >= d) ? sums[t - d] : 0;
            __syncthreads();
            if (t >= d) sums[t] += v;
            __syncthreads();
        }
        int excl = (t == 0) ? 0 : sums[t - 1];
#pragma unroll
        for (int i = 0; i < 20; i++) {
            int idx = base + i;
            if (idx < NN) g_cur_s[idx] = excl + local[i];
        }
        __syncthreads();
    }
    {
        int local[20]; int s = 0;
#pragma unroll
        for (int i = 0; i < 20; i++) {
            int idx = base + i;
            int c = (idx < NN) ? g_cnt_d[idx] : 0;
            local[i] = s; s += c;
        }
        sums[t] = s;
        __syncthreads();
        for (int d = 1; d < 1024; d <<= 1) {
            int v = (t >= d) ? sums[t - d] : 0;
            __syncthreads();
            if (t >= d) sums[t] += v;
            __syncthreads();
        }
        int excl = (t == 0) ? 0 : sums[t - 1];
#pragma unroll
        for (int i = 0; i < 20; i++) {
            int idx = base + i;
            if (idx < NN) { g_cur_d[idx] = excl + local[i]; g_start_d[idx] = excl + local[i]; }
        }
    }
}

__global__ void k_fill(const int* __restrict__ ei) {
    int e = blockIdx.x * blockDim.x + threadIdx.x;
    if (e >= NE) return;
    int src = ei[e];
    int dst = ei[NE + e];
    int pd = atomicAdd(&g_cur_d[dst], 1);
    g_deid[pd] = e;
    g_desrc[pd] = src;
    int ps = atomicAdd(&g_cur_s[src], 1);
    g_sperm[ps] = e;
    g_ssrc[ps] = src;
    g_spos[ps] = pd;
}

// -------- nodeY: y = A1 * (x @ W), weights in registers ----------------------
__global__ void __launch_bounds__(448) k_nodeY_a(
    const float* __restrict__ x, const float* __restrict__ W1)
{
    __shared__ float xs[NA];
    float wreg[NA];
#pragma unroll
    for (int u = 0; u < NA; u++) wreg[u] = W1[u * 448 + threadIdx.x];
    int v = threadIdx.x / M0;
    int w = threadIdx.x % M0;

    for (int n = blockIdx.x; n < NN; n += gridDim.x) {
        __syncthreads();
        if (threadIdx.x < NA) xs[threadIdx.x] = x[n * NA + threadIdx.x];
        __syncthreads();
        float r = 0.f;
#pragma unroll
        for (int u = 0; u < NA; u++) r = fmaf(xs[u], wreg[u], r);
        g_y[(long long)n * YDIM + v * MTOT + w] = A1 * r;
    }
}

__global__ void __launch_bounds__(320) k_nodeY_b(
    const float* __restrict__ x, const float* __restrict__ W2,
    const float* __restrict__ W3)
{
    __shared__ float xs[NA];
    bool active = threadIdx.x < 280;
    int v = threadIdx.x / 40;
    int j = threadIdx.x % 40;
    float wreg[NA];
    if (active) {
#pragma unroll
        for (int u = 0; u < NA; u++)
            wreg[u] = (j < M1) ? W2[(u * NB + v) * M1 + j]
                               : W3[(u * NB + v) * M2 + (j - M1)];
    }
    for (int n = blockIdx.x; n < NN; n += gridDim.x) {
        __syncthreads();
        if (threadIdx.x < NA) xs[threadIdx.x] = x[n * NA + threadIdx.x];
        __syncthreads();
        if (!active) continue;
        float r = 0.f;
#pragma unroll
        for (int u = 0; u < NA; u++) r = fmaf(xs[u], wreg[u], r);
        g_y[(long long)n * YDIM + v * MTOT + 64 + j] = A1 * r;
    }
}

// -------- tcomp: t[pd, 0:104] = sum_v ea[e,v] * y[src, v, :], src-sorted -----
__global__ void __launch_bounds__(256) k_tcomp(const float* __restrict__ ea)
{
    int gid = blockIdx.x * 256 + threadIdx.x;
    int p = gid >> 1;
    int half = gid & 1;
    if (p >= NE) return;
    int e = g_sperm[p];
    int src = g_ssrc[p];
    int pd = g_spos[p];

    float4 acc[13];
#pragma unroll
    for (int i = 0; i < 13; i++) acc[i] = make_float4(0.f, 0.f, 0.f, 0.f);

    const float* yrow = g_y + (long long)src * YDIM + half * 52;
#pragma unroll
    for (int v = 0; v < NB; v++) {
        float eav = __ldg(ea + e * NB + v);
        const float4* yp = (const float4*)(yrow + v * MTOT);
#pragma unroll
        for (int i = 0; i < 13; i++) {
            float4 yv = __ldg(yp + i);
            acc[i].x = fmaf(eav, yv.x, acc[i].x);
            acc[i].y = fmaf(eav, yv.y, acc[i].y);
            acc[i].z = fmaf(eav, yv.z, acc[i].z);
            acc[i].w = fmaf(eav, yv.w, acc[i].w);
        }
    }
    float4* tp = (float4*)(g_t + (long long)pd * MTOT + half * 52);
#pragma unroll
    for (int i = 0; i < 13; i++) tp[i] = acc[i];
}

// -------- accum: warp per dst node, register accumulation, fused nodeV -------
// Lane groups: 0-7: sh0 (w 0..63); 8-16: sh1 (w 64..87, m=(l-8)/3);
// 17-26: sh2 (w 88..103, m=(l-17)/2). Each lane: 8 contiguous t floats.
__global__ void __launch_bounds__(256) k_accum(
    const float* __restrict__ pos, const float* __restrict__ V1,
    const float* __restrict__ V2, const float* __restrict__ V3)
{
    __shared__ float Vs[728];
    __shared__ float nf_sh[8][216];

    int tid = threadIdx.x;
    int warp = tid >> 5;
    int lane = tid & 31;

    for (int i = tid; i < 728; i += 256)
        Vs[i] = (i < 448) ? V1[i] : (i < 616) ? V2[i - 448] : V3[i - 616];
    __syncthreads();

    int n = blockIdx.x * 8 + warp;
    if (n >= NN) return;

    // lane-invariant mapping
    int wbase, sidx;   // sidx: 0..2 sh1, 3..7 sh2, 8 => 1.0
    if (lane < 8)       { wbase = lane * 8;              sidx = 8; }
    else if (lane < 17) { int q = lane - 8;  wbase = 64 + (q % 3) * 8; sidx = q / 3; }
    else if (lane < 27) { int q = lane - 17; wbase = 88 + (q % 2) * 8; sidx = 3 + q / 2; }
    else                { wbase = 0; sidx = 8; }

    int start = g_start_d[n];
    int cnt = g_cnt_d[n];

    float dx = __ldg(pos + n*3+0), dy = __ldg(pos + n*3+1), dz = __ldg(pos + n*3+2);

    float acc[8];
#pragma unroll
    for (int k = 0; k < 8; k++) acc[k] = 0.f;

    const float* trow = g_t + (long long)start * MTOT + wbase;

    for (int i = 0; i < cnt; i++) {
        int s = g_desrc[start + i];                       // warp-broadcast
        float px = __ldg(pos + s*3+0) - dx;
        float py = __ldg(pos + s*3+1) - dy;
        float pz = __ldg(pos + s*3+2) - dz;
        float r2 = px*px + py*py + pz*pz;
        float s0 = S3*px, s1 = S3*py, s2 = S3*pz;
        float s3v = S15*px*py, s4 = S15*py*pz;
        float s5v = 0.5f*S5*(3.f*pz*pz - r2);
        float s6 = S15*px*pz, s7 = 0.5f*S15*(px*px - py*py);
        // select tree (sidx loop-invariant -> SETPs hoisted, SELs remain)
        float mult = (sidx < 4) ? ((sidx < 2) ? (sidx == 0 ? s0 : s1)
                                              : (sidx == 2 ? s2 : s3v))
                                : ((sidx < 6) ? (sidx == 4 ? s4 : s5v)
                                              : ((sidx == 6) ? s6 : (sidx == 7 ? s7 : 1.0f)));

        const float4* tp = (const float4*)(trow + (long long)i * MTOT);
        float4 t0 = __ldg(tp);
        float4 t1 = __ldg(tp + 1);
        acc[0] = fmaf(mult, t0.x, acc[0]);
        acc[1] = fmaf(mult, t0.y, acc[1]);
        acc[2] = fmaf(mult, t0.z, acc[2]);
        acc[3] = fmaf(mult, t0.w, acc[3]);
        acc[4] = fmaf(mult, t1.x, acc[4]);
        acc[5] = fmaf(mult, t1.y, acc[5]);
        acc[6] = fmaf(mult, t1.z, acc[6]);
        acc[7] = fmaf(mult, t1.w, acc[7]);
    }

    // writeback to per-warp nf in original layout
    if (lane < 8) {
#pragma unroll
        for (int k = 0; k < 8; k++) nf_sh[warp][lane * 8 + k] = acc[k];
    } else if (lane < 17) {
        int q = lane - 8; int m = q / 3; int li = q % 3;
#pragma unroll
        for (int k = 0; k < 8; k++) {
            int u = li * 8 + k;
            nf_sh[warp][OFF1 + u * 3 + m] = acc[k];
        }
    } else if (lane < 27) {
        int q = lane - 17; int m = q / 2; int li = q % 2;
#pragma unroll
        for (int k = 0; k < 8; k++) {
            int u = li * 8 + k;
            nf_sh[warp][OFF2 + u * 5 + m] = acc[k];
        }
    }
    __syncwarp();

    const float* nf = nf_sh[warp];
    for (int k = lane; k < 63; k += 32) {
        float r = 0.f;
        if (k < 7) {
            int v = k;
            for (int u = 0; u < M0; u++) r = fmaf(nf[u], Vs[u * NB + v], r);
            r *= C0;
        } else if (k < 28) {
            int t2 = k - 7; int v = t2 / 3; int m = t2 - 3 * v;
            for (int u = 0; u < M1; u++) r = fmaf(nf[OFF1 + u*3 + m], Vs[448 + u*NB + v], r);
            r *= C1;
        } else {
            int t2 = k - 28; int v = t2 / 5; int m = t2 - 5 * v;
            for (int u = 0; u < M2; u++) r = fmaf(nf[OFF2 + u*5 + m], Vs[616 + u*NB + v], r);
            r *= C2;
        }
        g_m[(long long)n * MDIM + k] = r;
    }
}

// -------- pass2: warp per dst node over CSR, fused graph reduction -----------
__global__ void __launch_bounds__(256) k_pass2(
    const float* __restrict__ pos, const float* __restrict__ ea,
    const int* __restrict__ batch, float* __restrict__ out)
{
    int warp = (blockIdx.x * 256 + threadIdx.x) >> 5;
    int lane = threadIdx.x & 31;
    if (warp >= NN) return;
    int n = warp;
    int start = g_start_d[n];
    int cnt = g_cnt_d[n];

    float dpx = pos[n*3+0], dpy = pos[n*3+1], dpz = pos[n*3+2];
    float gsum = 0.f;

    for (int i = lane; i < cnt; i += 32) {
        int e = g_deid[start + i];
        int s = g_desrc[start + i];

        float px = pos[s*3+0] - dpx;
        float py = pos[s*3+1] - dpy;
        float pz = pos[s*3+2] - dpz;
        float sh1x = S3*px, sh1y = S3*py, sh1z = S3*pz;
        float r2 = px*px + py*py + pz*pz;
        float sh2_0 = S15*px*py;
        float sh2_1 = S15*py*pz;
        float sh2_2 = 0.5f*S5*(3.f*pz*pz - r2);
        float sh2_3 = S15*px*pz;
        float sh2_4 = 0.5f*S15*(px*px - py*py);

        float eav[NB];
#pragma unroll
        for (int v = 0; v < NB; v++) eav[v] = __ldg(ea + e * NB + v);

        float mreg[64];
        const float4* mp = (const float4*)(g_m + (long long)s * MDIM);
#pragma unroll
        for (int q = 0; q < 16; q++) ((float4*)mreg)[q] = __ldg(mp + q);

        float g = 0.f;
#pragma unroll
        for (int v = 0; v < NB; v++) {
            const float* m1v = mreg + 7 + v*3;
            const float* m2v = mreg + 28 + v*5;
            float t = mreg[v];
            t = fmaf(sh1x, m1v[0], t);
            t = fmaf(sh1y, m1v[1], t);
            t = fmaf(sh1z, m1v[2], t);
            t = fmaf(sh2_0, m2v[0], t);
            t = fmaf(sh2_1, m2v[1], t);
            t = fmaf(sh2_2, m2v[2], t);
            t = fmaf(sh2_3, m2v[3], t);
            t = fmaf(sh2_4, m2v[4], t);
            g = fmaf(eav[v], t, g);
        }
        gsum += g;
    }

#pragma unroll
    for (int off = 16; off > 0; off >>= 1)
        gsum += __shfl_xor_sync(0xFFFFFFFFu, gsum, off);

    if (lane == 0) atomicAdd(&out[batch[n]], gsum);
}

extern "C" void kernel_launch(void* const* d_in, const int* in_sizes, int n_in,
                              void* d_out, int out_size) {
    const float* pos   = (const float*)d_in[0];
    const float* x     = (const float*)d_in[1];
    const float* ea    = (const float*)d_in[2];
    const int*   ei    = (const int*)d_in[3];
    const int*   batch = (const int*)d_in[4];
    const float* W1    = (const float*)d_in[5];
    const float* W2    = (const float*)d_in[6];
    const float* W3    = (const float*)d_in[7];
    const float* V1    = (const float*)d_in[8];
    const float* V2    = (const float*)d_in[9];
    const float* V3    = (const float*)d_in[10];
    float* out = (float*)d_out;

    k_zero<<<160, 256>>>(out);
    k_count<<<(NE + 255) / 256, 256>>>(ei);
    k_scan<<<1, 1024>>>();
    k_fill<<<(NE + 255) / 256, 256>>>(ei);
    k_nodeY_a<<<1184, 448>>>(x, W1);
    k_nodeY_b<<<1184, 320>>>(x, W2, W3);
    k_tcomp<<<(2 * NE) / 256, 256>>>(ea);
    k_accum<<<(NN + 7) / 8, 256>>>(pos, V1, V2, V3);
    k_pass2<<<(NN * 32) / 256, 256>>>(pos, ea, batch, out);
}

// round 7
// speedup vs baseline: 2.3289x; 1.7228x over previous
#include <cuda_runtime.h>

#define NN 20000
#define NE 320000
#define NG 256
#define NA 23
#define NB 7
#define M0 64
#define M1 24
#define M2 16
#define MDIM 64

__device__ __align__(16) float g_wv[3381];                 // WV[(jv*7+v)*23 + u]
__device__ __align__(16) float g_yv[(size_t)NN * 168];     // yv[n][jv(21)*8 + v(7)]
__device__ __align__(16) float g_ead[(size_t)NE * 8];      // dst-sorted ea, padded
__device__ __align__(16) float g_shd[(size_t)NE * 8];      // dst-sorted sh1(3),sh2(5)
__device__ __align__(16) float g_m[(size_t)NN * MDIM];
__device__ int g_cnt_d[NN], g_cur_d[NN], g_start_d[NN];
__device__ int g_desrc[NE];

#define A1  0.078811041f
#define C0  0.047245559f
#define C1  0.044543540f
#define C2  0.042257713f
#define S3  1.7320508075688772f
#define S5  2.23606797749979f
#define S15 3.872983346207417f

__global__ void k_zero(float* __restrict__ out) {
    int i = blockIdx.x * blockDim.x + threadIdx.x;
    int stride = gridDim.x * blockDim.x;
    for (int j = i; j < NN; j += stride) g_cnt_d[j] = 0;
    for (int j = i; j < NG; j += stride) out[j] = 0.f;
}

__global__ void k_count(const int* __restrict__ ei) {
    int e = blockIdx.x * blockDim.x + threadIdx.x;
    if (e < NE) atomicAdd(&g_cnt_d[ei[NE + e]], 1);
}

__global__ void __launch_bounds__(1024) k_scan() {
    __shared__ int sums[1024];
    int t = threadIdx.x;
    int base = t * 20;
    int local[20]; int s = 0;
#pragma unroll
    for (int i = 0; i < 20; i++) {
        int idx = base + i;
        int c = (idx < NN) ? g_cnt_d[idx] : 0;
        local[i] = s; s += c;
    }
    sums[t] = s;
    __syncthreads();
    for (int d = 1; d < 1024; d <<= 1) {
        int v = (t >= d) ? sums[t - d] : 0;
        __syncthreads();
        if (t >= d) sums[t] += v;
        __syncthreads();
    }
    int excl = (t == 0) ? 0 : sums[t - 1];
#pragma unroll
    for (int i = 0; i < 20; i++) {
        int idx = base + i;
        if (idx < NN) { g_cur_d[idx] = excl + local[i]; g_start_d[idx] = excl + local[i]; }
    }
}

// fill: dst-sort edges; stage ea (padded) and sh per edge at dst position
__global__ void k_fill(const int* __restrict__ ei, const float* __restrict__ ea,
                       const float* __restrict__ pos) {
    int e = blockIdx.x * blockDim.x + threadIdx.x;
    if (e >= NE) return;
    int src = ei[e];
    int dst = ei[NE + e];
    int pd = atomicAdd(&g_cur_d[dst], 1);
    g_desrc[pd] = src;

    float a0 = __ldg(ea + e*7 + 0), a1 = __ldg(ea + e*7 + 1);
    float a2 = __ldg(ea + e*7 + 2), a3 = __ldg(ea + e*7 + 3);
    float a4 = __ldg(ea + e*7 + 4), a5 = __ldg(ea + e*7 + 5);
    float a6 = __ldg(ea + e*7 + 6);
    float4* eap = (float4*)(g_ead + (size_t)pd * 8);
    eap[0] = make_float4(a0, a1, a2, a3);
    eap[1] = make_float4(a4, a5, a6, 0.f);

    float px = __ldg(pos + src*3+0) - __ldg(pos + dst*3+0);
    float py = __ldg(pos + src*3+1) - __ldg(pos + dst*3+1);
    float pz = __ldg(pos + src*3+2) - __ldg(pos + dst*3+2);
    float r2 = px*px + py*py + pz*pz;
    float4* shp = (float4*)(g_shd + (size_t)pd * 8);
    shp[0] = make_float4(S3*px, S3*py, S3*pz, S15*px*py);
    shp[1] = make_float4(S15*py*pz, 0.5f*S5*(3.f*pz*pz - r2),
                         S15*px*pz, 0.5f*S15*(px*px - py*py));
}

// WV[(jv*7+v)*23+u] = scale_j * sum_w W_j[u,v,w] * V_j[w, v'],  jv = j*7+v'
__global__ void k_wv(const float* __restrict__ W1, const float* __restrict__ W2,
                     const float* __restrict__ W3, const float* __restrict__ V1,
                     const float* __restrict__ V2, const float* __restrict__ V3) {
    int o = blockIdx.x * 512 + threadIdx.x;
    if (o >= 3381) return;
    int u = o % 23;
    int t = o / 23;
    int v = t % 7;
    int jv = t / 7;
    int j = jv / 7, vp = jv % 7;
    float r = 0.f;
    if (j == 0) {
        for (int w = 0; w < M0; w++) r = fmaf(W1[(u*7+v)*M0 + w], V1[w*7 + vp], r);
        r *= A1 * C0;
    } else if (j == 1) {
        for (int w = 0; w < M1; w++) r = fmaf(W2[(u*7+v)*M1 + w], V2[w*7 + vp], r);
        r *= A1 * C1;
    } else {
        for (int w = 0; w < M2; w++) r = fmaf(W3[(u*7+v)*M2 + w], V3[w*7 + vp], r);
        r *= A1 * C2;
    }
    g_wv[o] = r;
}

// yv[n, jv*8 + v] = sum_u x[n,u] * WV[(jv*7+v)*23 + u]
__global__ void __launch_bounds__(160) k_yv(const float* __restrict__ x) {
    __shared__ float xs[NA];
    int t = threadIdx.x;
    bool act = t < 147;
    float wreg[NA];
    if (act) {
#pragma unroll
        for (int u = 0; u < NA; u++) wreg[u] = g_wv[t * 23 + u];
    }
    int jv = t / 7, v = t % 7;
    int off = jv * 8 + v;
    for (int n = blockIdx.x; n < NN; n += gridDim.x) {
        __syncthreads();
        if (t < NA) xs[t] = x[n * NA + t];
        __syncthreads();
        if (!act) continue;
        float r = 0.f;
#pragma unroll
        for (int u = 0; u < NA; u++) r = fmaf(xs[u], wreg[u], r);
        g_yv[(size_t)n * 168 + off] = r;
    }
}

__device__ __forceinline__ float shsel(float4 h0, float4 h1, int si) {
    float a = (si == 0) ? h0.x : (si == 1) ? h0.y : (si == 2) ? h0.z : h0.w;
    float b = (si == 4) ? h1.x : (si == 5) ? h1.y : (si == 6) ? h1.z : h1.w;
    float c = (si < 4) ? a : b;
    return (si >= 8) ? 1.f : c;
}

// warp per dst node: m[n, o] = sum_{e->n} sh(e, o) * sum_v ea[e,v]*yv[src, jv(o), v]
__global__ void __launch_bounds__(256) k_maccum() {
    int warp = (blockIdx.x * 256 + threadIdx.x) >> 5;
    int lane = threadIdx.x & 31;
    if (warp >= NN) return;
    int n = warp;
    int start = g_start_d[n];
    int cnt = g_cnt_d[n];

    int o0 = lane, o1 = lane + 32;
    int jv0, si0, jv1 = 0, si1 = 8;
    if (o0 < 7)       { jv0 = o0; si0 = 8; }
    else if (o0 < 28) { int q = o0 - 7;  jv0 = 7 + q / 3;  si0 = q % 3; }
    else              { int q = o0 - 28; jv0 = 14 + q / 5; si0 = 3 + q % 5; }
    bool v1ok = o1 < 63;
    if (v1ok) {
        if (o1 < 28) { int q = o1 - 7;  jv1 = 7 + q / 3;  si1 = q % 3; }
        else         { int q = o1 - 28; jv1 = 14 + q / 5; si1 = 3 + q % 5; }
    }

    float acc0 = 0.f, acc1 = 0.f;
    for (int i = 0; i < cnt; i++) {
        int base = start + i;
        const float4* eap = (const float4*)(g_ead + (size_t)base * 8);
        float4 a0 = __ldg(eap), a1v = __ldg(eap + 1);
        const float4* shp = (const float4*)(g_shd + (size_t)base * 8);
        float4 h0 = __ldg(shp), h1 = __ldg(shp + 1);
        int s = g_desrc[base];
        const float* yb = g_yv + (size_t)s * 168;
        {
            const float4* yp = (const float4*)(yb + jv0 * 8);
            float4 y0 = __ldg(yp), y1 = __ldg(yp + 1);
            float z = a0.x*y0.x + a0.y*y0.y + a0.z*y0.z + a0.w*y0.w
                    + a1v.x*y1.x + a1v.y*y1.y + a1v.z*y1.z;
            acc0 = fmaf(z, shsel(h0, h1, si0), acc0);
        }
        if (v1ok) {
            const float4* yp = (const float4*)(yb + jv1 * 8);
            float4 y0 = __ldg(yp), y1 = __ldg(yp + 1);
            float z = a0.x*y0.x + a0.y*y0.y + a0.z*y0.z + a0.w*y0.w
                    + a1v.x*y1.x + a1v.y*y1.y + a1v.z*y1.z;
            acc1 = fmaf(z, shsel(h0, h1, si1), acc1);
        }
    }
    g_m[(size_t)n * MDIM + o0] = acc0;
    if (v1ok) g_m[(size_t)n * MDIM + o1] = acc1;
    else if (lane == 31) g_m[(size_t)n * MDIM + 63] = 0.f;
}

// pass2: warp per dst node; g = sum_v ea[v]*(m0 + sh1.m1 + sh2.m2)[src]
__global__ void __launch_bounds__(256) k_pass2(
    const int* __restrict__ batch, float* __restrict__ out)
{
    int warp = (blockIdx.x * 256 + threadIdx.x) >> 5;
    int lane = threadIdx.x & 31;
    if (warp >= NN) return;
    int n = warp;
    int start = g_start_d[n];
    int cnt = g_cnt_d[n];

    float gsum = 0.f;
    for (int i = lane; i < cnt; i += 32) {
        int base = start + i;
        const float4* eap = (const float4*)(g_ead + (size_t)base * 8);
        float4 a0 = __ldg(eap), a1v = __ldg(eap + 1);
        const float4* shp = (const float4*)(g_shd + (size_t)base * 8);
        float4 h0 = __ldg(shp), h1 = __ldg(shp + 1);
        int s = g_desrc[base];

        float eav[NB] = { a0.x, a0.y, a0.z, a0.w, a1v.x, a1v.y, a1v.z };
        float mreg[64];
        const float4* mp = (const float4*)(g_m + (size_t)s * MDIM);
#pragma unroll
        for (int q = 0; q < 16; q++) ((float4*)mreg)[q] = __ldg(mp + q);

        float g = 0.f;
#pragma unroll
        for (int v = 0; v < NB; v++) {
            const float* m1v = mreg + 7 + v * 3;
            const float* m2v = mreg + 28 + v * 5;
            float t = mreg[v];
            t = fmaf(h0.x, m1v[0], t);
            t = fmaf(h0.y, m1v[1], t);
            t = fmaf(h0.z, m1v[2], t);
            t = fmaf(h0.w, m2v[0], t);
            t = fmaf(h1.x, m2v[1], t);
            t = fmaf(h1.y, m2v[2], t);
            t = fmaf(h1.z, m2v[3], t);
            t = fmaf(h1.w, m2v[4], t);
            g = fmaf(eav[v], t, g);
        }
        gsum += g;
    }

#pragma unroll
    for (int off = 16; off > 0; off >>= 1)
        gsum += __shfl_xor_sync(0xFFFFFFFFu, gsum, off);

    if (lane == 0) atomicAdd(&out[batch[n]], gsum);
}

extern "C" void kernel_launch(void* const* d_in, const int* in_sizes, int n_in,
                              void* d_out, int out_size) {
    const float* pos   = (const float*)d_in[0];
    const float* x     = (const float*)d_in[1];
    const float* ea    = (const float*)d_in[2];
    const int*   ei    = (const int*)d_in[3];
    const int*   batch = (const int*)d_in[4];
    const float* W1    = (const float*)d_in[5];
    const float* W2    = (const float*)d_in[6];
    const float* W3    = (const float*)d_in[7];
    const float* V1    = (const float*)d_in[8];
    const float* V2    = (const float*)d_in[9];
    const float* V3    = (const float*)d_in[10];
    float* out = (float*)d_out;

    k_zero<<<80, 256>>>(out);
    k_count<<<(NE + 255) / 256, 256>>>(ei);
    k_scan<<<1, 1024>>>();
    k_fill<<<(NE + 255) / 256, 256>>>(ei, ea, pos);
    k_wv<<<7, 512>>>(W1, W2, W3, V1, V2, V3);
    k_yv<<<1480, 160>>>(x);
    k_maccum<<<(NN * 32 + 255) / 256, 256>>>();
    k_pass2<<<(NN * 32 + 255) / 256, 256>>>(batch, out);
}